// round 12
// baseline (speedup 1.0000x reference)
#include <cuda_runtime.h>
#include <cuda.h>
#include <cstdint>

// ---------------- problem constants ----------------
#define NN     10000
#define CC     128
#define NADJ   3
#define NSLOPE 0.2f

#define KCH64   64
#define NCH64   157                          // ceil(10000/64)
#define NSPLIT  11
#define MTILES  ((NN + 127) / 128)           // 79
#define MPAD    (MTILES * 128)
#define WPR     (313 * 16)                   // 5008 words per channel row (fp16 pairs)

#define SUB_BYTES   8192                     // one 32-k plane: 128 rows x 16 words
#define BSTAGE_BYTES (2 * SUB_BYTES)         // 16 KB per 64-k stage
#define STAGES_B    4
#define MIX_BYTES   (2 * SUB_BYTES)          // 16 KB per 64-k mix buffer
#define DYNSMEM     (STAGES_B * BSTAGE_BYTES + 2 * MIX_BYTES + 1024)

// scratch (static device arrays — zero-initialized, no allocation)
__device__ __align__(1024) uint32_t g_sup_w[CC * WPR];         // supᵀ fp16, permuted+rotated
__device__ __align__(16)   float g_part[NSPLIT][MPAD][CC];     // split-K partials

// ---------------- helpers ----------------
__device__ __forceinline__ uint32_t smem_u32(const void* p) {
    uint32_t a;
    asm("{ .reg .u64 t; cvta.to.shared.u64 t, %1; cvt.u32.u64 %0, t; }" : "=r"(a) : "l"(p));
    return a;
}
// pack two fp32 -> fp16x2 (lo = first arg)
__device__ __forceinline__ uint32_t h2pack(float lo, float hi) {
    uint32_t d;
    asm("cvt.rn.f16x2.f32 %0, %1, %2;" : "=r"(d) : "f"(hi), "f"(lo));
    return d;
}
__device__ __forceinline__ void lds_b64(uint32_t a, uint32_t& lo, uint32_t& hi) {
    asm volatile("ld.shared.v2.b32 {%0, %1}, [%2];" : "=r"(lo), "=r"(hi) : "r"(a));
}
__device__ __forceinline__ void sts_b128(uint32_t a, uint32_t r0, uint32_t r1,
                                         uint32_t r2, uint32_t r3) {
    asm volatile("st.shared.v4.b32 [%0], {%1, %2, %3, %4};"
        :: "r"(a), "r"(r0), "r"(r1), "r"(r2), "r"(r3) : "memory");
}

#define MBARRIER_INIT(addr, cnt) \
    asm volatile("mbarrier.init.shared.b64 [%0], %1;" :: "r"(addr), "r"(cnt) : "memory")
#define MBARRIER_EXPECT_TX(addr, bytes) \
    asm volatile("mbarrier.arrive.expect_tx.shared.b64 _, [%0], %1;" :: "r"(addr), "r"(bytes) : "memory")
#define MBARRIER_ARRIVE(addr) \
    asm volatile("mbarrier.arrive.shared.b64 _, [%0];" :: "r"(addr) : "memory")

#define MBARRIER_WAIT_PARITY(mbar, par) do {                                      \
    uint32_t _m = (mbar), _p = (par), _d;                                         \
    asm volatile("{\n\t.reg .pred p;\n\t"                                         \
        "mbarrier.try_wait.parity.acquire.cta.shared::cta.b64 p, [%1], %2;\n\t"   \
        "selp.b32 %0, 1, 0, p;\n\t}" : "=r"(_d) : "r"(_m), "r"(_p) : "memory");   \
    if (!_d) {                                                                    \
        asm volatile("{\n\t.reg .pred P1;\n\t"                                    \
            "W_%=:\n\t"                                                           \
            "mbarrier.try_wait.parity.acquire.cta.shared::cta.b64 P1, [%0], %1, 0x989680;\n\t" \
            "@P1 bra.uni D_%=;\n\t"                                               \
            "bra.uni W_%=;\n\t"                                                   \
            "D_%=:\n\t}" :: "r"(_m), "r"(_p) : "memory");                         \
    } } while (0)

#define MBARRIER_WAIT_PARITY_RELAXED(mbar, par) do {                              \
    uint32_t _m = (mbar), _p = (par), _d;                                         \
    asm volatile("{\n\t.reg .pred p;\n\t"                                         \
        "mbarrier.try_wait.parity.relaxed.cta.shared::cta.b64 p, [%1], %2, 0x989680;\n\t" \
        "selp.b32 %0, 1, 0, p;\n\t}" : "=r"(_d) : "r"(_m), "r"(_p) : "memory");   \
    if (!_d) {                                                                    \
        asm volatile("{\n\t.reg .pred P1;\n\t"                                    \
            "W_%=:\n\t"                                                           \
            "mbarrier.try_wait.parity.relaxed.cta.shared::cta.b64 P1, [%0], %1, 0x989680;\n\t" \
            "@P1 bra.uni D_%=;\n\t"                                               \
            "bra.uni W_%=;\n\t"                                                   \
            "D_%=:\n\t}" :: "r"(_m), "r"(_p) : "memory");                         \
    } } while (0)

#define TMA_LOAD_3D(sa, tmap, x, y, z, mbar)                                      \
    asm volatile("cp.async.bulk.tensor.3d.shared::cta.global.tile.mbarrier::complete_tx::bytes " \
        "[%0], [%1, {%2, %3, %4}], [%5];"                                         \
        :: "r"((uint32_t)(sa)), "l"(tmap), "r"((int)(x)), "r"((int)(y)),          \
           "r"((int)(z)), "r"((uint32_t)(mbar)) : "memory")

// mma.sync m16n8k16 f16 with fp32 accumulate (baseline PTX, sm_80+)
__device__ __forceinline__ void mma_f16(float* c, const uint32_t* A,
                                        uint32_t b0, uint32_t b1) {
    asm volatile(
        "mma.sync.aligned.m16n8k16.row.col.f32.f16.f16.f32 "
        "{%0,%1,%2,%3}, {%4,%5,%6,%7}, {%8,%9}, {%0,%1,%2,%3};"
        : "+f"(c[0]), "+f"(c[1]), "+f"(c[2]), "+f"(c[3])
        : "r"(A[0]), "r"(A[1]), "r"(A[2]), "r"(A[3]), "r"(b0), "r"(b1));
}

// Per-32k-plane layout (identical to the R9/R11 proven layout):
//   16 words/row; blocks j=0..3 at pos ((j+row)&3)*4; block holds (w2j, w2j+4, w2j+1, w2j+5)
//   (+8 word offset for j>=2). Consumer thread q, step ks2 reads pair via one LDS.64 at
//   block (2ks2 + (q>>1)), inner (q&1)*2.

// ---------------- kernel 1: support = X@W + b ; fp16 permuted transposed copy ------
__global__ void __launch_bounds__(128)
k_support(const float* __restrict__ inp, const float* __restrict__ w,
          const float* __restrict__ b) {
    __shared__ float in_s[8][CC];
    __shared__ float s_out[CC][9];
    const int t  = threadIdx.x;
    const int n0 = blockIdx.x * 8;

    #pragma unroll
    for (int j = 0; j < 8; ++j)
        in_s[j][t] = inp[(n0 + j) * CC + t];
    __syncthreads();

    float acc[8];
    #pragma unroll
    for (int j = 0; j < 8; ++j) acc[j] = 0.f;
    const float bc = b[t];
    #pragma unroll 4
    for (int i = 0; i < CC; ++i) {
        const float wv = w[i * CC + t];
        #pragma unroll
        for (int j = 0; j < 8; ++j) acc[j] = fmaf(in_s[j][i], wv, acc[j]);
    }
    #pragma unroll
    for (int j = 0; j < 8; ++j) s_out[t][j] = acc[j] + bc;
    __syncthreads();

    const int w4    = t & 3;
    const int c0    = t >> 2;              // 32 channels per pass
    const int chunk = n0 >> 5;
    const int wbase = (n0 & 31) >> 1;      // {0,4,8,12}
    const int wg    = wbase + w4;          // word index within chunk, 0..15
    const int jblk  = ((wg >> 3) << 1) | ((wg >> 1) & 1);
    const int r4    = wg & 7;
    const int inner = (r4 & 1) * 2 + (r4 >> 2);
    #pragma unroll
    for (int cc = 0; cc < CC; cc += 32) {
        const int c = cc + c0;
        const int pos = (((jblk + c) & 3) << 2) | inner;
        g_sup_w[(size_t)c * WPR + chunk * 16 + pos] =
            h2pack(s_out[c][2 * w4], s_out[c][2 * w4 + 1]);
    }
}

// ---------------- kernel 2: split-K fp16 HMMA GEMM, KCH=64 (two proven planes) -----
__device__ __forceinline__ void load_premix_pack(
    const float* __restrict__ arow, int kbase,
    float at0, float at1, float at2, int off1, int off2, uint32_t pk[2][4]) {
    #pragma unroll
    for (int sub = 0; sub < 2; ++sub) {
        const int k0 = kbase + sub * 32;
        const bool o1 = (k0 + off1 + 4 <= NN), o2 = (k0 + off2 + 4 <= NN);
        float4 pa[NADJ], pb[NADJ];
        #pragma unroll
        for (int t = 0; t < NADJ; ++t) {
            const float* p0 = arow + (size_t)t * NN * NN + k0;
            pa[t] = o1 ? *reinterpret_cast<const float4*>(p0 + off1) : make_float4(0.f,0.f,0.f,0.f);
            pb[t] = o2 ? *reinterpret_cast<const float4*>(p0 + off2) : make_float4(0.f,0.f,0.f,0.f);
        }
        float4 ma, mb;
        ma.x = fmaf(at2, pa[2].x, fmaf(at1, pa[1].x, at0 * pa[0].x));
        ma.y = fmaf(at2, pa[2].y, fmaf(at1, pa[1].y, at0 * pa[0].y));
        ma.z = fmaf(at2, pa[2].z, fmaf(at1, pa[1].z, at0 * pa[0].z));
        ma.w = fmaf(at2, pa[2].w, fmaf(at1, pa[1].w, at0 * pa[0].w));
        mb.x = fmaf(at2, pb[2].x, fmaf(at1, pb[1].x, at0 * pb[0].x));
        mb.y = fmaf(at2, pb[2].y, fmaf(at1, pb[1].y, at0 * pb[0].y));
        mb.z = fmaf(at2, pb[2].z, fmaf(at1, pb[1].z, at0 * pb[0].z));
        mb.w = fmaf(at2, pb[2].w, fmaf(at1, pb[1].w, at0 * pb[0].w));
        pk[sub][0] = h2pack(ma.x, ma.y);
        pk[sub][1] = h2pack(mb.x, mb.y);
        pk[sub][2] = h2pack(ma.z, ma.w);
        pk[sub][3] = h2pack(mb.z, mb.w);
    }
}

__global__ void __launch_bounds__(512, 1)
k_gemm(const __grid_constant__ CUtensorMap tmap_b,
       const float* __restrict__ adj,
       const float* __restrict__ att) {
    extern __shared__ __align__(1024) char dsm[];
    __shared__ __align__(8) uint64_t bars[2 * STAGES_B];

    const int tid  = threadIdx.x;
    const int wid  = tid >> 5;
    const int lane = tid & 31;
    const int g    = lane >> 2;
    const int q    = lane & 3;
    const int m0   = blockIdx.x * 128;
    const int sidx = blockIdx.y;

    const uint32_t dbase   = (smem_u32(dsm) + 1023u) & ~1023u;
    const uint32_t mixbase = dbase + STAGES_B * BSTAGE_BYTES;
    const uint32_t Bfull   = smem_u32(bars);
    const uint32_t Bempty  = Bfull + 8 * STAGES_B;

    if (tid == 0) {
        for (int s = 0; s < STAGES_B; ++s) {
            MBARRIER_INIT(Bfull + 8 * s, 1);
            MBARRIER_INIT(Bempty + 8 * s, 512);
        }
        asm volatile("fence.proxy.async.shared::cta;" ::: "memory");
    }
    __syncthreads();

    const float at0 = att[0], at1 = att[1], at2 = att[2];
    const int nch = (NCH64 - sidx + NSPLIT - 1) / NSPLIT;

    // ---- B TMA prologue: two 8KB planes per 64-k stage ----
    if (tid == 0) {
        const int pre = (nch < STAGES_B) ? nch : STAGES_B;
        for (int i = 0; i < pre; ++i) {
            MBARRIER_EXPECT_TX(Bfull + 8 * i, (uint32_t)BSTAGE_BYTES);
            const int x0 = (sidx + i * NSPLIT) * 32;          // word coordinate
            TMA_LOAD_3D(dbase + i * BSTAGE_BYTES,             &tmap_b, x0,      0, 0, Bfull + 8 * i);
            TMA_LOAD_3D(dbase + i * BSTAGE_BYTES + SUB_BYTES, &tmap_b, x0 + 16, 0, 0, Bfull + 8 * i);
        }
    }

    // producer mapping: 4 threads/row; thread j owns block j (8 k per plane)
    const int r  = tid >> 2;
    const int j  = tid & 3;
    const int mrow = (m0 + r < NN) ? (m0 + r) : (NN - 1);
    const int off1 = ((j & 1) << 2) + ((j >> 1) << 4);   // {0,4,16,20}
    const int off2 = off1 + 8;                            // {8,12,24,28}
    const float* arow = adj + (size_t)mrow * NN;
    const uint32_t sts_addr_off = ((uint32_t)r * 16 + (uint32_t)(((j + r) & 3) << 2)) * 4;

    const int wm = wid & 3;
    const int wn = wid >> 2;

    float acc[2][4][4];
    #pragma unroll
    for (int mi = 0; mi < 2; ++mi)
        #pragma unroll
        for (int ni = 0; ni < 4; ++ni)
            #pragma unroll
            for (int rr = 0; rr < 4; ++rr) acc[mi][ni][rr] = 0.f;

    uint32_t pk[2][4];

    // ---- prologue: chunk 0 premixed+packed, STS to buf0; then pack chunk 1 ----
    load_premix_pack(arow, sidx * KCH64, at0, at1, at2, off1, off2, pk);
    sts_b128(mixbase + sts_addr_off,             pk[0][0], pk[0][1], pk[0][2], pk[0][3]);
    sts_b128(mixbase + SUB_BYTES + sts_addr_off, pk[1][0], pk[1][1], pk[1][2], pk[1][3]);
    if (nch > 1)
        load_premix_pack(arow, (sidx + NSPLIT) * KCH64, at0, at1, at2, off1, off2, pk);
    __syncthreads();

    for (int it = 0; it < nch; ++it) {
        const int s = it & (STAGES_B - 1);
        const uint32_t mixcur = mixbase + (uint32_t)(it & 1) * MIX_BYTES;

        // ---- STS chunk it+1 (packed last iteration); LDG+premix+pack chunk it+2 ----
        if (it + 1 < nch) {
            const uint32_t mixnext = mixbase + (uint32_t)((it + 1) & 1) * MIX_BYTES;
            sts_b128(mixnext + sts_addr_off,             pk[0][0], pk[0][1], pk[0][2], pk[0][3]);
            sts_b128(mixnext + SUB_BYTES + sts_addr_off, pk[1][0], pk[1][1], pk[1][2], pk[1][3]);
            if (it + 2 < nch)
                load_premix_pack(arow, (sidx + (it + 2) * NSPLIT) * KCH64,
                                 at0, at1, at2, off1, off2, pk);
        }

        // ---- MMA chunk it (two planes) ----
        MBARRIER_WAIT_PARITY(Bfull + 8 * s, (it / STAGES_B) & 1);
        const uint32_t Bb = dbase + s * BSTAGE_BYTES;

        #pragma unroll
        for (int sub = 0; sub < 2; ++sub) {
            const uint32_t mc = mixcur + (uint32_t)sub * SUB_BYTES;
            const uint32_t Bs = Bb + (uint32_t)sub * SUB_BYTES;
            #pragma unroll
            for (int ks2 = 0; ks2 < 2; ++ks2) {
                const int blk = ks2 * 2 + (q >> 1);
                const uint32_t inn = (uint32_t)((q & 1) * 2);
                uint32_t amix[2][4];
                #pragma unroll
                for (int mi = 0; mi < 2; ++mi) {
                    const int r0 = wm * 32 + mi * 16 + g;
                    lds_b64(mc + ((uint32_t)r0 * 16 + (uint32_t)(((blk + r0) & 3) << 2) + inn) * 4,
                            amix[mi][0], amix[mi][2]);
                    const int r1 = r0 + 8;
                    lds_b64(mc + ((uint32_t)r1 * 16 + (uint32_t)(((blk + r1) & 3) << 2) + inn) * 4,
                            amix[mi][1], amix[mi][3]);
                }
                #pragma unroll
                for (int ni = 0; ni < 4; ++ni) {
                    const int cn = wn * 32 + ni * 8 + g;
                    uint32_t b0, b1;
                    lds_b64(Bs + ((uint32_t)cn * 16 + (uint32_t)(((blk + cn) & 3) << 2) + inn) * 4,
                            b0, b1);
                    mma_f16(acc[0][ni], amix[0], b0, b1);
                    mma_f16(acc[1][ni], amix[1], b0, b1);
                }
            }
        }

        MBARRIER_ARRIVE(Bempty + 8 * s);

        if (tid == 0 && it + STAGES_B < nch) {
            MBARRIER_WAIT_PARITY_RELAXED(Bempty + 8 * s, (it / STAGES_B) & 1);
            MBARRIER_EXPECT_TX(Bfull + 8 * s, (uint32_t)BSTAGE_BYTES);
            const int x0 = (sidx + (it + STAGES_B) * NSPLIT) * 32;
            TMA_LOAD_3D(Bb,             &tmap_b, x0,      0, 0, Bfull + 8 * s);
            TMA_LOAD_3D(Bb + SUB_BYTES, &tmap_b, x0 + 16, 0, 0, Bfull + 8 * s);
        }

        __syncthreads();
    }

    // ---- write split-K partials ----
    float* pbase = &g_part[sidx][0][0];
    #pragma unroll
    for (int mi = 0; mi < 2; ++mi) {
        #pragma unroll
        for (int ni = 0; ni < 4; ++ni) {
            const int rr = m0 + wm * 32 + mi * 16 + g;
            const int c  = wn * 32 + ni * 8 + q * 2;
            float2 v0 = make_float2(acc[mi][ni][0], acc[mi][ni][1]);
            float2 v1 = make_float2(acc[mi][ni][2], acc[mi][ni][3]);
            *reinterpret_cast<float2*>(pbase + (size_t)rr * CC + c)       = v0;
            *reinterpret_cast<float2*>(pbase + (size_t)(rr + 8) * CC + c) = v1;
        }
    }
}

// ---------------- kernel 3: reduce split-K partials + LeakyReLU --------------------
__global__ void __launch_bounds__(256)
k_reduce(float* __restrict__ out) {
    const int idx = blockIdx.x * 256 + threadIdx.x;
    const int total = NN * CC / 4;
    if (idx >= total) return;
    const int n  = idx / (CC / 4);
    const int c4 = (idx % (CC / 4)) * 4;

    float4 s = make_float4(0.f, 0.f, 0.f, 0.f);
    #pragma unroll
    for (int k = 0; k < NSPLIT; ++k) {
        const float4 v = *reinterpret_cast<const float4*>(&g_part[k][n][c4]);
        s.x += v.x; s.y += v.y; s.z += v.z; s.w += v.w;
    }
    s.x = (s.x >= 0.f) ? s.x : NSLOPE * s.x;
    s.y = (s.y >= 0.f) ? s.y : NSLOPE * s.y;
    s.z = (s.z >= 0.f) ? s.z : NSLOPE * s.z;
    s.w = (s.w >= 0.f) ? s.w : NSLOPE * s.w;
    *reinterpret_cast<float4*>(&out[(size_t)n * CC + c4]) = s;
}

// dummies: position k_gemm as 4th launch (6th overall) so ncu -s 5 -c 1 profiles it
__global__ void k_dummy() {}
__global__ void k_dummy2() {}

// ---------------- host launch ----------------
typedef CUresult (*PFN_encodeTiled)(
    CUtensorMap*, CUtensorMapDataType, cuuint32_t, void*,
    const cuuint64_t*, const cuuint64_t*, const cuuint32_t*, const cuuint32_t*,
    CUtensorMapInterleave, CUtensorMapSwizzle, CUtensorMapL2promotion,
    CUtensorMapFloatOOBfill);

extern "C" void kernel_launch(void* const* d_in, const int* in_sizes, int n_in,
                              void* d_out, int out_size) {
    const float *inp = nullptr, *adj = nullptr, *att = nullptr, *w = nullptr, *b = nullptr;
    for (int i = 0; i < n_in; ++i) {
        switch (in_sizes[i]) {
            case NN * CC:        inp = (const float*)d_in[i]; break;
            case NADJ * NN * NN: adj = (const float*)d_in[i]; break;
            case NADJ:           att = (const float*)d_in[i]; break;
            case CC * CC:        w   = (const float*)d_in[i]; break;
            case CC:             b   = (const float*)d_in[i]; break;
            default: break;
        }
    }
    float* out = (float*)d_out;

    k_support<<<NN / 8, 128>>>(inp, w, b);
    k_dummy<<<1, 32>>>();
    k_dummy2<<<1, 32>>>();

    PFN_encodeTiled enc = nullptr;
    {
        void* p = nullptr;
        cudaDriverEntryPointQueryResult st;
#if CUDART_VERSION >= 12050
        cudaGetDriverEntryPointByVersion("cuTensorMapEncodeTiled", &p, 12000,
                                         cudaEnableDefault, &st);
#else
        cudaGetDriverEntryPoint("cuTensorMapEncodeTiled", &p, cudaEnableDefault, &st);
#endif
        enc = (PFN_encodeTiled)p;
    }
    void* supw_ptr = nullptr;
    cudaGetSymbolAddress(&supw_ptr, g_sup_w);

    CUtensorMap tb;
    cuuint32_t box[3] = {16, 128, 1};      // 16 words (64B) x 128 channel rows
    cuuint32_t es[3]  = {1, 1, 1};
    {   // B: g_sup_w [CC][WPR] uint32 words, inner dim = words (permuted fp16 pairs)
        cuuint64_t dims[3] = {WPR, CC, 1};
        cuuint64_t str[2]  = {(cuuint64_t)WPR * 4, (cuuint64_t)CC * WPR * 4};
        enc(&tb, CU_TENSOR_MAP_DATA_TYPE_UINT32, 3, supw_ptr, dims, str, box, es,
            CU_TENSOR_MAP_INTERLEAVE_NONE, CU_TENSOR_MAP_SWIZZLE_NONE,
            CU_TENSOR_MAP_L2_PROMOTION_L2_128B, CU_TENSOR_MAP_FLOAT_OOB_FILL_NONE);
    }

    cudaFuncSetAttribute(k_gemm, cudaFuncAttributeMaxDynamicSharedMemorySize, DYNSMEM);
    dim3 grid(MTILES, NSPLIT);
    k_gemm<<<grid, 512, DYNSMEM>>>(tb, adj, att);

    k_reduce<<<(NN * CC / 4 + 255) / 256, 256>>>(out);
}

// round 13
// speedup vs baseline: 1.0836x; 1.0836x over previous
#include <cuda_runtime.h>
#include <cuda.h>
#include <cuda_fp16.h>
#include <cstdint>

// ---------------- problem constants ----------------
#define NN     10000
#define CC     128
#define NADJ   3
#define NSLOPE 0.2f

#define KCH     32
#define NCHUNK  ((NN + KCH - 1) / KCH)      // 313
#define NSPLIT  11
#define MTILES  ((NN + 127) / 128)          // 79
#define MPAD    (MTILES * 128)
#define WPR     (NCHUNK * 16)               // 5008 uint32 words per channel row (fp16 pairs)

#define BTILE_BYTES 8192                    // 128 c-rows x 16 words (fp16 halves)
#define STAGES_B    4
#define MIX_BYTES   8192                    // 128 m-rows x 16 words
#define DYNSMEM     (STAGES_B * BTILE_BYTES + 2 * MIX_BYTES + 1024)

// scratch (static device arrays — zero-initialized, no allocation)
__device__ __align__(1024) uint32_t g_sup_w[CC * WPR];           // supᵀ fp16, permuted+rotated
__device__ __align__(16)   uint32_t g_parth[NSPLIT][MPAD][CC/2]; // split-K partials, fp16x2

// ---------------- helpers ----------------
__device__ __forceinline__ uint32_t smem_u32(const void* p) {
    uint32_t a;
    asm("{ .reg .u64 t; cvta.to.shared.u64 t, %1; cvt.u32.u64 %0, t; }" : "=r"(a) : "l"(p));
    return a;
}
// pack two fp32 -> fp16x2 (lo = first arg)
__device__ __forceinline__ uint32_t h2pack(float lo, float hi) {
    uint32_t d;
    asm("cvt.rn.f16x2.f32 %0, %1, %2;" : "=r"(d) : "f"(hi), "f"(lo));
    return d;
}
__device__ __forceinline__ void lds_b64(uint32_t a, uint32_t& lo, uint32_t& hi) {
    asm volatile("ld.shared.v2.b32 {%0, %1}, [%2];" : "=r"(lo), "=r"(hi) : "r"(a));
}
__device__ __forceinline__ void sts_b128(uint32_t a, uint32_t r0, uint32_t r1,
                                         uint32_t r2, uint32_t r3) {
    asm volatile("st.shared.v4.b32 [%0], {%1, %2, %3, %4};"
        :: "r"(a), "r"(r0), "r"(r1), "r"(r2), "r"(r3) : "memory");
}

#define MBARRIER_INIT(addr, cnt) \
    asm volatile("mbarrier.init.shared.b64 [%0], %1;" :: "r"(addr), "r"(cnt) : "memory")
#define MBARRIER_EXPECT_TX(addr, bytes) \
    asm volatile("mbarrier.arrive.expect_tx.shared.b64 _, [%0], %1;" :: "r"(addr), "r"(bytes) : "memory")
#define MBARRIER_ARRIVE(addr) \
    asm volatile("mbarrier.arrive.shared.b64 _, [%0];" :: "r"(addr) : "memory")

#define MBARRIER_WAIT_PARITY(mbar, par) do {                                      \
    uint32_t _m = (mbar), _p = (par), _d;                                         \
    asm volatile("{\n\t.reg .pred p;\n\t"                                         \
        "mbarrier.try_wait.parity.acquire.cta.shared::cta.b64 p, [%1], %2;\n\t"   \
        "selp.b32 %0, 1, 0, p;\n\t}" : "=r"(_d) : "r"(_m), "r"(_p) : "memory");   \
    if (!_d) {                                                                    \
        asm volatile("{\n\t.reg .pred P1;\n\t"                                    \
            "W_%=:\n\t"                                                           \
            "mbarrier.try_wait.parity.acquire.cta.shared::cta.b64 P1, [%0], %1, 0x989680;\n\t" \
            "@P1 bra.uni D_%=;\n\t"                                               \
            "bra.uni W_%=;\n\t"                                                   \
            "D_%=:\n\t}" :: "r"(_m), "r"(_p) : "memory");                         \
    } } while (0)

#define MBARRIER_WAIT_PARITY_RELAXED(mbar, par) do {                              \
    uint32_t _m = (mbar), _p = (par), _d;                                         \
    asm volatile("{\n\t.reg .pred p;\n\t"                                         \
        "mbarrier.try_wait.parity.relaxed.cta.shared::cta.b64 p, [%1], %2, 0x989680;\n\t" \
        "selp.b32 %0, 1, 0, p;\n\t}" : "=r"(_d) : "r"(_m), "r"(_p) : "memory");   \
    if (!_d) {                                                                    \
        asm volatile("{\n\t.reg .pred P1;\n\t"                                    \
            "W_%=:\n\t"                                                           \
            "mbarrier.try_wait.parity.relaxed.cta.shared::cta.b64 P1, [%0], %1, 0x989680;\n\t" \
            "@P1 bra.uni D_%=;\n\t"                                               \
            "bra.uni W_%=;\n\t"                                                   \
            "D_%=:\n\t}" :: "r"(_m), "r"(_p) : "memory");                         \
    } } while (0)

#define TMA_LOAD_3D(sa, tmap, x, y, z, mbar)                                      \
    asm volatile("cp.async.bulk.tensor.3d.shared::cta.global.tile.mbarrier::complete_tx::bytes " \
        "[%0], [%1, {%2, %3, %4}], [%5];"                                         \
        :: "r"((uint32_t)(sa)), "l"(tmap), "r"((int)(x)), "r"((int)(y)),          \
           "r"((int)(z)), "r"((uint32_t)(mbar)) : "memory")

// mma.sync m16n8k16 f16 with fp32 accumulate (baseline PTX, sm_80+)
__device__ __forceinline__ void mma_f16(float* c, const uint32_t* A,
                                        uint32_t b0, uint32_t b1) {
    asm volatile(
        "mma.sync.aligned.m16n8k16.row.col.f32.f16.f16.f32 "
        "{%0,%1,%2,%3}, {%4,%5,%6,%7}, {%8,%9}, {%0,%1,%2,%3};"
        : "+f"(c[0]), "+f"(c[1]), "+f"(c[2]), "+f"(c[3])
        : "r"(A[0]), "r"(A[1]), "r"(A[2]), "r"(A[3]), "r"(b0), "r"(b1));
}

// Layout (per 32-k chunk = 16 uint32 words, per row, both A-mix and B):
//   blocks j=0..3 of 4 words; block j stored at pos ((j+row)&3)*4.
//   block content: j<2: (w_{2j}, w_{2j+4}, w_{2j+1}, w_{2j+5});
//                  j>=2: same with +8 word offset (second k16 step).
//   Consumer thread q, k-step ks2: pair (w_{8ks2+q}, w_{8ks2+q+4}) is one LDS.64 at
//   block (2ks2 + (q>>1)), inner (q&1)*2.   word w holds halves k=2w, 2w+1.

// ---------------- kernel 1: support = X@W + b ; fp16 permuted transposed copy ------
__global__ void __launch_bounds__(128)
k_support(const float* __restrict__ inp, const float* __restrict__ w,
          const float* __restrict__ b) {
    __shared__ float in_s[8][CC];
    __shared__ float s_out[CC][9];
    const int t  = threadIdx.x;
    const int n0 = blockIdx.x * 8;

    #pragma unroll
    for (int j = 0; j < 8; ++j)
        in_s[j][t] = inp[(n0 + j) * CC + t];
    __syncthreads();

    float acc[8];
    #pragma unroll
    for (int j = 0; j < 8; ++j) acc[j] = 0.f;
    const float bc = b[t];
    #pragma unroll 4
    for (int i = 0; i < CC; ++i) {
        const float wv = w[i * CC + t];
        #pragma unroll
        for (int j = 0; j < 8; ++j) acc[j] = fmaf(in_s[j][i], wv, acc[j]);
    }
    #pragma unroll
    for (int j = 0; j < 8; ++j) s_out[t][j] = acc[j] + bc;
    __syncthreads();

    const int w4    = t & 3;
    const int c0    = t >> 2;              // 32 channels per pass
    const int chunk = n0 >> 5;
    const int wbase = (n0 & 31) >> 1;      // {0,4,8,12}
    const int wg    = wbase + w4;          // word index within chunk, 0..15
    const int jblk  = ((wg >> 3) << 1) | ((wg >> 1) & 1);
    const int r4    = wg & 7;
    const int inner = (r4 & 1) * 2 + (r4 >> 2);
    #pragma unroll
    for (int cc = 0; cc < CC; cc += 32) {
        const int c = cc + c0;
        const int pos = (((jblk + c) & 3) << 2) | inner;
        g_sup_w[(size_t)c * WPR + chunk * 16 + pos] =
            h2pack(s_out[c][2 * w4], s_out[c][2 * w4 + 1]);
    }
}

// ---------------- kernel 2: split-K fp16 HMMA GEMM, pipelined (R9-exact mainloop) --
__global__ void __launch_bounds__(512, 1)
k_gemm(const __grid_constant__ CUtensorMap tmap_b,
       const float* __restrict__ adj,
       const float* __restrict__ att) {
    extern __shared__ __align__(1024) char dsm[];
    __shared__ __align__(8) uint64_t bars[2 * STAGES_B];

    const int tid  = threadIdx.x;
    const int wid  = tid >> 5;
    const int lane = tid & 31;
    const int g    = lane >> 2;
    const int q    = lane & 3;
    const int m0   = blockIdx.x * 128;
    const int sidx = blockIdx.y;

    const uint32_t dbase   = (smem_u32(dsm) + 1023u) & ~1023u;
    const uint32_t mixbase = dbase + STAGES_B * BTILE_BYTES;
    const uint32_t Bfull   = smem_u32(bars);
    const uint32_t Bempty  = Bfull + 8 * STAGES_B;

    if (tid == 0) {
        for (int s = 0; s < STAGES_B; ++s) {
            MBARRIER_INIT(Bfull + 8 * s, 1);
            MBARRIER_INIT(Bempty + 8 * s, 512);
        }
        asm volatile("fence.proxy.async.shared::cta;" ::: "memory");
    }
    __syncthreads();

    const float at0 = att[0], at1 = att[1], at2 = att[2];
    const int nch = (NCHUNK - sidx + NSPLIT - 1) / NSPLIT;

    // ---- B TMA prologue ----
    if (tid == 0) {
        const int pre = (nch < STAGES_B) ? nch : STAGES_B;
        for (int i = 0; i < pre; ++i) {
            MBARRIER_EXPECT_TX(Bfull + 8 * i, (uint32_t)BTILE_BYTES);
            TMA_LOAD_3D(dbase + i * BTILE_BYTES, &tmap_b,
                        (sidx + i * NSPLIT) * 16, 0, 0, Bfull + 8 * i);
        }
    }

    // producer mapping: 4 threads/row; thread j owns block j (8 k-values)
    const int r  = tid >> 2;
    const int j  = tid & 3;
    const int mrow = (m0 + r < NN) ? (m0 + r) : (NN - 1);
    const int off1 = ((j & 1) << 2) + ((j >> 1) << 4);   // {0,4,16,20}
    const int off2 = off1 + 8;                            // {8,12,24,28}
    const float* arow = adj + (size_t)mrow * NN;
    const uint32_t sts_addr_off = ((uint32_t)r * 16 + (uint32_t)(((j + r) & 3) << 2)) * 4;

    const int wm = wid & 3;
    const int wn = wid >> 2;

    float acc[2][4][4];
    #pragma unroll
    for (int mi = 0; mi < 2; ++mi)
        #pragma unroll
        for (int ni = 0; ni < 4; ++ni)
            #pragma unroll
            for (int rr = 0; rr < 4; ++rr) acc[mi][ni][rr] = 0.f;

    float4 pfa[NADJ], pfb[NADJ];

    // ---- prologue: premix chunk 0 -> buf0; prefetch chunk 1 ----
    {
        const int k0 = sidx * KCH;
        const bool ok1 = (k0 + off1 + 4 <= NN), ok2 = (k0 + off2 + 4 <= NN);
        #pragma unroll
        for (int t = 0; t < NADJ; ++t) {
            const float* p0 = arow + (size_t)t * NN * NN + k0;
            pfa[t] = ok1 ? *reinterpret_cast<const float4*>(p0 + off1) : make_float4(0.f,0.f,0.f,0.f);
            pfb[t] = ok2 ? *reinterpret_cast<const float4*>(p0 + off2) : make_float4(0.f,0.f,0.f,0.f);
        }
        float4 ma, mb;
        ma.x = fmaf(at2, pfa[2].x, fmaf(at1, pfa[1].x, at0 * pfa[0].x));
        ma.y = fmaf(at2, pfa[2].y, fmaf(at1, pfa[1].y, at0 * pfa[0].y));
        ma.z = fmaf(at2, pfa[2].z, fmaf(at1, pfa[1].z, at0 * pfa[0].z));
        ma.w = fmaf(at2, pfa[2].w, fmaf(at1, pfa[1].w, at0 * pfa[0].w));
        mb.x = fmaf(at2, pfb[2].x, fmaf(at1, pfb[1].x, at0 * pfb[0].x));
        mb.y = fmaf(at2, pfb[2].y, fmaf(at1, pfb[1].y, at0 * pfb[0].y));
        mb.z = fmaf(at2, pfb[2].z, fmaf(at1, pfb[1].z, at0 * pfb[0].z));
        mb.w = fmaf(at2, pfb[2].w, fmaf(at1, pfb[1].w, at0 * pfb[0].w));
        sts_b128(mixbase + sts_addr_off,
                 h2pack(ma.x, ma.y), h2pack(mb.x, mb.y),
                 h2pack(ma.z, ma.w), h2pack(mb.z, mb.w));
        if (nch > 1) {
            const int k1 = (sidx + NSPLIT) * KCH;
            const bool o1 = (k1 + off1 + 4 <= NN), o2 = (k1 + off2 + 4 <= NN);
            #pragma unroll
            for (int t = 0; t < NADJ; ++t) {
                const float* p0 = arow + (size_t)t * NN * NN + k1;
                pfa[t] = o1 ? *reinterpret_cast<const float4*>(p0 + off1) : make_float4(0.f,0.f,0.f,0.f);
                pfb[t] = o2 ? *reinterpret_cast<const float4*>(p0 + off2) : make_float4(0.f,0.f,0.f,0.f);
            }
        }
    }
    __syncthreads();

    for (int it = 0; it < nch; ++it) {
        const int s = it & (STAGES_B - 1);
        const uint32_t mixcur = mixbase + (uint32_t)(it & 1) * MIX_BYTES;

        // ---- premix + STS chunk it+1 (overlaps MMA below) ----
        if (it + 1 < nch) {
            const uint32_t mixnext = mixbase + (uint32_t)((it + 1) & 1) * MIX_BYTES;
            float4 ma, mb;
            ma.x = fmaf(at2, pfa[2].x, fmaf(at1, pfa[1].x, at0 * pfa[0].x));
            ma.y = fmaf(at2, pfa[2].y, fmaf(at1, pfa[1].y, at0 * pfa[0].y));
            ma.z = fmaf(at2, pfa[2].z, fmaf(at1, pfa[1].z, at0 * pfa[0].z));
            ma.w = fmaf(at2, pfa[2].w, fmaf(at1, pfa[1].w, at0 * pfa[0].w));
            mb.x = fmaf(at2, pfb[2].x, fmaf(at1, pfb[1].x, at0 * pfb[0].x));
            mb.y = fmaf(at2, pfb[2].y, fmaf(at1, pfb[1].y, at0 * pfb[0].y));
            mb.z = fmaf(at2, pfb[2].z, fmaf(at1, pfb[1].z, at0 * pfb[0].z));
            mb.w = fmaf(at2, pfb[2].w, fmaf(at1, pfb[1].w, at0 * pfb[0].w));
            sts_b128(mixnext + sts_addr_off,
                     h2pack(ma.x, ma.y), h2pack(mb.x, mb.y),
                     h2pack(ma.z, ma.w), h2pack(mb.z, mb.w));
            if (it + 2 < nch) {
                const int k0n = (sidx + (it + 2) * NSPLIT) * KCH;
                const bool o1 = (k0n + off1 + 4 <= NN), o2 = (k0n + off2 + 4 <= NN);
                #pragma unroll
                for (int t = 0; t < NADJ; ++t) {
                    const float* p0 = arow + (size_t)t * NN * NN + k0n;
                    pfa[t] = o1 ? *reinterpret_cast<const float4*>(p0 + off1) : make_float4(0.f,0.f,0.f,0.f);
                    pfb[t] = o2 ? *reinterpret_cast<const float4*>(p0 + off2) : make_float4(0.f,0.f,0.f,0.f);
                }
            }
        }

        // ---- MMA chunk it ----
        MBARRIER_WAIT_PARITY(Bfull + 8 * s, (it / STAGES_B) & 1);
        const uint32_t Bb = dbase + s * BTILE_BYTES;

        #pragma unroll
        for (int ks2 = 0; ks2 < 2; ++ks2) {
            const int blk = ks2 * 2 + (q >> 1);
            const uint32_t inn = (uint32_t)((q & 1) * 2);
            uint32_t amix[2][4];
            #pragma unroll
            for (int mi = 0; mi < 2; ++mi) {
                const int r0 = wm * 32 + mi * 16 + g;
                lds_b64(mixcur + ((uint32_t)r0 * 16 + (uint32_t)(((blk + r0) & 3) << 2) + inn) * 4,
                        amix[mi][0], amix[mi][2]);
                const int r1 = r0 + 8;
                lds_b64(mixcur + ((uint32_t)r1 * 16 + (uint32_t)(((blk + r1) & 3) << 2) + inn) * 4,
                        amix[mi][1], amix[mi][3]);
            }
            #pragma unroll
            for (int ni = 0; ni < 4; ++ni) {
                const int cn = wn * 32 + ni * 8 + g;
                uint32_t b0, b1;
                lds_b64(Bb + ((uint32_t)cn * 16 + (uint32_t)(((blk + cn) & 3) << 2) + inn) * 4,
                        b0, b1);
                mma_f16(acc[0][ni], amix[0], b0, b1);
                mma_f16(acc[1][ni], amix[1], b0, b1);
            }
        }

        MBARRIER_ARRIVE(Bempty + 8 * s);

        if (tid == 0 && it + STAGES_B < nch) {
            MBARRIER_WAIT_PARITY_RELAXED(Bempty + 8 * s, (it / STAGES_B) & 1);
            MBARRIER_EXPECT_TX(Bfull + 8 * s, (uint32_t)BTILE_BYTES);
            TMA_LOAD_3D(Bb, &tmap_b, (sidx + (it + STAGES_B) * NSPLIT) * 16, 0, 0, Bfull + 8 * s);
        }

        __syncthreads();
    }

    // ---- write split-K partials (fp16x2 — halves partial traffic) ----
    #pragma unroll
    for (int mi = 0; mi < 2; ++mi) {
        #pragma unroll
        for (int ni = 0; ni < 4; ++ni) {
            const int rr = m0 + wm * 32 + mi * 16 + g;
            const int c  = wn * 32 + ni * 8 + q * 2;
            g_parth[sidx][rr][c >> 1]     = h2pack(acc[mi][ni][0], acc[mi][ni][1]);
            g_parth[sidx][rr + 8][c >> 1] = h2pack(acc[mi][ni][2], acc[mi][ni][3]);
        }
    }
}

// ---------------- kernel 3: reduce fp16 split-K partials + LeakyReLU ---------------
__global__ void __launch_bounds__(256)
k_reduce(float* __restrict__ out) {
    const int idx = blockIdx.x * 256 + threadIdx.x;   // one uint4 = 8 channels
    const int total = NN * CC / 8;
    if (idx >= total) return;
    const int n  = idx / (CC / 8);
    const int w0 = (idx % (CC / 8)) * 4;              // word base (half2 words)

    float s[8];
    #pragma unroll
    for (int i = 0; i < 8; ++i) s[i] = 0.f;
    #pragma unroll
    for (int k = 0; k < NSPLIT; ++k) {
        const uint4 v = *reinterpret_cast<const uint4*>(&g_parth[k][n][w0]);
        const float2 f0 = __half22float2(*reinterpret_cast<const __half2*>(&v.x));
        const float2 f1 = __half22float2(*reinterpret_cast<const __half2*>(&v.y));
        const float2 f2 = __half22float2(*reinterpret_cast<const __half2*>(&v.z));
        const float2 f3 = __half22float2(*reinterpret_cast<const __half2*>(&v.w));
        s[0] += f0.x; s[1] += f0.y; s[2] += f1.x; s[3] += f1.y;
        s[4] += f2.x; s[5] += f2.y; s[6] += f3.x; s[7] += f3.y;
    }
    #pragma unroll
    for (int i = 0; i < 8; ++i) s[i] = (s[i] >= 0.f) ? s[i] : NSLOPE * s[i];
    float4 o0 = make_float4(s[0], s[1], s[2], s[3]);
    float4 o1 = make_float4(s[4], s[5], s[6], s[7]);
    *reinterpret_cast<float4*>(&out[(size_t)n * CC + w0 * 2])     = o0;
    *reinterpret_cast<float4*>(&out[(size_t)n * CC + w0 * 2 + 4]) = o1;
}

// dummies: position k_gemm as 4th launch (6th overall) so ncu -s 5 -c 1 profiles it
__global__ void k_dummy() {}
__global__ void k_dummy2() {}

// ---------------- host launch ----------------
typedef CUresult (*PFN_encodeTiled)(
    CUtensorMap*, CUtensorMapDataType, cuuint32_t, void*,
    const cuuint64_t*, const cuuint64_t*, const cuuint32_t*, const cuuint32_t*,
    CUtensorMapInterleave, CUtensorMapSwizzle, CUtensorMapL2promotion,
    CUtensorMapFloatOOBfill);

extern "C" void kernel_launch(void* const* d_in, const int* in_sizes, int n_in,
                              void* d_out, int out_size) {
    const float *inp = nullptr, *adj = nullptr, *att = nullptr, *w = nullptr, *b = nullptr;
    for (int i = 0; i < n_in; ++i) {
        switch (in_sizes[i]) {
            case NN * CC:        inp = (const float*)d_in[i]; break;
            case NADJ * NN * NN: adj = (const float*)d_in[i]; break;
            case NADJ:           att = (const float*)d_in[i]; break;
            case CC * CC:        w   = (const float*)d_in[i]; break;
            case CC:             b   = (const float*)d_in[i]; break;
            default: break;
        }
    }
    float* out = (float*)d_out;

    k_support<<<NN / 8, 128>>>(inp, w, b);
    k_dummy<<<1, 32>>>();
    k_dummy2<<<1, 32>>>();

    PFN_encodeTiled enc = nullptr;
    {
        void* p = nullptr;
        cudaDriverEntryPointQueryResult st;
#if CUDART_VERSION >= 12050
        cudaGetDriverEntryPointByVersion("cuTensorMapEncodeTiled", &p, 12000,
                                         cudaEnableDefault, &st);
#else
        cudaGetDriverEntryPoint("cuTensorMapEncodeTiled", &p, cudaEnableDefault, &st);
#endif
        enc = (PFN_encodeTiled)p;
    }
    void* supw_ptr = nullptr;
    cudaGetSymbolAddress(&supw_ptr, g_sup_w);

    CUtensorMap tb;
    cuuint32_t box[3] = {16, 128, 1};      // 16 words (64B) x 128 channel rows
    cuuint32_t es[3]  = {1, 1, 1};
    {   // B: g_sup_w [CC][WPR] uint32 words, inner dim = words (permuted fp16 pairs)
        cuuint64_t dims[3] = {WPR, CC, 1};
        cuuint64_t str[2]  = {(cuuint64_t)WPR * 4, (cuuint64_t)CC * WPR * 4};
        enc(&tb, CU_TENSOR_MAP_DATA_TYPE_UINT32, 3, supw_ptr, dims, str, box, es,
            CU_TENSOR_MAP_INTERLEAVE_NONE, CU_TENSOR_MAP_SWIZZLE_NONE,
            CU_TENSOR_MAP_L2_PROMOTION_L2_128B, CU_TENSOR_MAP_FLOAT_OOB_FILL_NONE);
    }

    cudaFuncSetAttribute(k_gemm, cudaFuncAttributeMaxDynamicSharedMemorySize, DYNSMEM);
    dim3 grid(MTILES, NSPLIT);
    k_gemm<<<grid, 512, DYNSMEM>>>(tb, adj, att);

    k_reduce<<<(NN * CC / 8 + 255) / 256, 256>>>(out);
}